// round 2
// baseline (speedup 1.0000x reference)
#include <cuda_runtime.h>

// Problem constants
#define BB    16
#define CC    8
#define DD    511
#define DIMN  2048
#define SEQ   512
#define NH    16
#define HD    128
#define HWSZ  256
#define XB    (CC*DD*HWSZ)   // 1046528  (x batch stride)
#define XC    (DD*HWSZ)      // 130816   (x channel stride)
#define QLD   6144           // qkv_w leading dim (row length)
#define SCALE 0.08838834764831845f  // 128^-0.5

// Scratch (static device globals; no allocation anywhere)
__device__ float g_q[DIMN];          // q for cls token (batch-independent)
__device__ float g_qhat[NH*DIMN];    // scale * Wk_h^T q_h
__device__ float g_sc[BB*NH*SEQ];    // scores -> probs (in place)
__device__ float g_t[BB*NH*DIMN];    // sum_s p * tok
__device__ float g_ao[BB*DIMN];      // attention output (pre-proj)

// ---------------------------------------------------------------------------
// Kernel 1: q[col] = (cls + pos[0]) . qkv_w[:, col] + qkv_b[col], col in [0,2048)
// grid 16, block 128
__global__ void k_q(const float* __restrict__ pos, const float* __restrict__ cls,
                    const float* __restrict__ qkvw, const float* __restrict__ qkvb) {
    __shared__ float tok0[DIMN];
    int tid = threadIdx.x;
    for (int i = tid; i < DIMN; i += 128) tok0[i] = cls[i] + pos[i];
    __syncthreads();
    int col = blockIdx.x * 128 + tid;
    float a0 = 0.f, a1 = 0.f, a2 = 0.f, a3 = 0.f;
    #pragma unroll 4
    for (int d = 0; d < DIMN; d += 4) {
        a0 += tok0[d+0] * qkvw[(d+0)*QLD + col];
        a1 += tok0[d+1] * qkvw[(d+1)*QLD + col];
        a2 += tok0[d+2] * qkvw[(d+2)*QLD + col];
        a3 += tok0[d+3] * qkvw[(d+3)*QLD + col];
    }
    g_q[col] = (a0 + a1) + (a2 + a3) + qkvb[col];
}

// ---------------------------------------------------------------------------
// Kernel 2: qhat[h, dim] = SCALE * sum_j qkv_w[dim, 2048 + h*128 + j] * q[h*128+j]
// grid (256, 16): 8 dims per CTA (warp each), block 256
__global__ void k_qhat(const float* __restrict__ qkvw) {
    int h = blockIdx.y;
    __shared__ float qv[HD];
    int tid = threadIdx.x;
    if (tid < HD) qv[tid] = g_q[h*HD + tid];
    __syncthreads();
    int w = tid >> 5, lane = tid & 31;
    int dim = blockIdx.x * 8 + w;
    const float* wr = qkvw + dim*QLD + DIMN + h*HD;
    float p = 0.f;
    #pragma unroll
    for (int j = lane; j < HD; j += 32) p += qv[j] * wr[j];
    #pragma unroll
    for (int o = 16; o; o >>= 1) p += __shfl_xor_sync(0xffffffffu, p, o);
    if (lane == 0) g_qhat[h*DIMN + dim] = p * SCALE;
}

// ---------------------------------------------------------------------------
// Kernel 3: scores[b,h,s] = qhat[h,:] . tok[b,s,:]  (tok built on the fly)
// grid (16 stiles, 16 b), block 256. Warp handles 4 tokens; lanes slice dims.
__global__ void k_scores(const float* __restrict__ x, const float* __restrict__ pos,
                         const float* __restrict__ cls) {
    int b = blockIdx.y;
    int tid = threadIdx.x, w = tid >> 5, lane = tid & 31;
    int s0 = blockIdx.x * 32 + w * 4;
    __shared__ float qh[NH * 512];

    float acc[NH][4];
    #pragma unroll
    for (int h = 0; h < NH; h++)
        #pragma unroll
        for (int j = 0; j < 4; j++) acc[h][j] = 0.f;

    for (int ch = 0; ch < 4; ch++) {
        for (int t = tid; t < NH*512; t += 256) {
            int h = t >> 9, dd = t & 511;
            qh[t] = g_qhat[h*DIMN + ch*512 + dd];
        }
        __syncthreads();
        #pragma unroll 2
        for (int it = 0; it < 16; it++) {
            int dd = it*32 + lane;
            int d  = ch*512 + dd;
            float tv[4];
            #pragma unroll
            for (int j = 0; j < 4; j++) {
                int s = s0 + j;
                float pv = pos[s*DIMN + d];
                float xv;
                if (s == 0) {
                    xv = cls[d];
                } else {
                    int c = d >> 8, r = d & 255;
                    xv = x[b*XB + c*XC + (s-1)*HWSZ + r];
                }
                tv[j] = xv + pv;
            }
            #pragma unroll
            for (int h = 0; h < NH; h++) {
                float qv = qh[h*512 + dd];
                #pragma unroll
                for (int j = 0; j < 4; j++) acc[h][j] += qv * tv[j];
            }
        }
        __syncthreads();
    }
    // butterfly reduce across the 32 lanes for all 64 outputs
    #pragma unroll
    for (int o = 16; o; o >>= 1) {
        #pragma unroll
        for (int h = 0; h < NH; h++)
            #pragma unroll
            for (int j = 0; j < 4; j++)
                acc[h][j] += __shfl_xor_sync(0xffffffffu, acc[h][j], o);
    }
    #pragma unroll
    for (int h = 0; h < NH; h++) {
        if (lane == h) {
            #pragma unroll
            for (int j = 0; j < 4; j++)
                g_sc[(b*NH + h)*SEQ + s0 + j] = acc[h][j];
        }
    }
}

// ---------------------------------------------------------------------------
// Kernel 4: softmax over s (512) per (b,h) row; adds the q.bk bias term.
// grid 256, block 128
__global__ void k_softmax(const float* __restrict__ qkvb) {
    int bh = blockIdx.x;
    int h = bh & 15;
    int tid = threadIdx.x;
    __shared__ float red[128];

    // sbias = SCALE * q_h . bk_h  (batch independent; zero in this dataset but kept general)
    red[tid] = g_q[h*HD + tid] * qkvb[DIMN + h*HD + tid];
    __syncthreads();
    for (int o = 64; o; o >>= 1) { if (tid < o) red[tid] += red[tid + o]; __syncthreads(); }
    float sbias = red[0] * SCALE;
    __syncthreads();

    float* row = g_sc + bh*SEQ;
    float v[4];
    float m = -1e30f;
    #pragma unroll
    for (int j = 0; j < 4; j++) { v[j] = row[tid + j*128] + sbias; m = fmaxf(m, v[j]); }
    red[tid] = m; __syncthreads();
    for (int o = 64; o; o >>= 1) { if (tid < o) red[tid] = fmaxf(red[tid], red[tid + o]); __syncthreads(); }
    m = red[0];
    __syncthreads();
    float s = 0.f;
    #pragma unroll
    for (int j = 0; j < 4; j++) { v[j] = expf(v[j] - m); s += v[j]; }
    red[tid] = s; __syncthreads();
    for (int o = 64; o; o >>= 1) { if (tid < o) red[tid] += red[tid + o]; __syncthreads(); }
    float inv = 1.f / red[0];
    #pragma unroll
    for (int j = 0; j < 4; j++) row[tid + j*128] = v[j] * inv;
}

// ---------------------------------------------------------------------------
// Kernel 5: t[b,h,dim] = sum_s p[b,h,s] * tok[b,s,dim]
// grid (8 dim-chunks, 16 b), block 256: thread owns one dim, all 16 heads in regs.
__global__ void k_t(const float* __restrict__ x, const float* __restrict__ pos,
                    const float* __restrict__ cls) {
    int b = blockIdx.y;
    int tid = threadIdx.x;
    int dim = blockIdx.x * 256 + tid;
    __shared__ float ps[NH*SEQ];  // 32 KB
    for (int t = tid; t < NH*SEQ; t += 256) ps[t] = g_sc[b*NH*SEQ + t];
    __syncthreads();

    int c = dim >> 8, r = dim & 255;
    const float* xp = x + b*XB + c*XC + r;   // token s>=1 -> xp[(s-1)*256]
    const float* pp = pos + dim;             // pp[s*DIMN]

    float acc[NH];
    #pragma unroll
    for (int h = 0; h < NH; h++) acc[h] = 0.f;

    // s = 0..3 scalar (s=0 is cls token)
    {
        float tv0 = cls[dim] + pp[0];
        float tv1 = xp[0*HWSZ] + pp[1*DIMN];
        float tv2 = xp[1*HWSZ] + pp[2*DIMN];
        float tv3 = xp[2*HWSZ] + pp[3*DIMN];
        #pragma unroll
        for (int h = 0; h < NH; h++) {
            const float* pr = ps + h*SEQ;
            acc[h] += pr[0]*tv0 + pr[1]*tv1 + pr[2]*tv2 + pr[3]*tv3;
        }
    }
    for (int k = 1; k < 128; k++) {
        int s = k*4;
        float tv[4];
        #pragma unroll
        for (int j = 0; j < 4; j++)
            tv[j] = xp[(s + j - 1)*HWSZ] + pp[(s + j)*DIMN];
        #pragma unroll
        for (int h = 0; h < NH; h++) {
            float4 p4 = *reinterpret_cast<const float4*>(&ps[h*SEQ + s]);
            acc[h] += p4.x*tv[0] + p4.y*tv[1] + p4.z*tv[2] + p4.w*tv[3];
        }
    }
    #pragma unroll
    for (int h = 0; h < NH; h++)
        g_t[(b*NH + h)*DIMN + dim] = acc[h];
}

// ---------------------------------------------------------------------------
// Kernel 6a: ao[b, h*128 + j] = t[b,h,:] . Wv[:, 4096 + h*128 + j] + bv
// grid (4 jblocks, 16 h), block 256. smem-staged tiles; Wv read exactly once.
__global__ void k_av(const float* __restrict__ qkvw, const float* __restrict__ qkvb) {
    int h = blockIdx.y, jb = blockIdx.x;
    int tid = threadIdx.x;
    int lane = tid & 31, grp = tid >> 5;  // grp handles b = grp and grp+8
    __shared__ float ts[16][128];
    __shared__ float ws[128][32];
    int col = 2*DIMN + h*HD + jb*32;
    float a0 = 0.f, a1 = 0.f;
    for (int chd = 0; chd < 16; chd++) {
        __syncthreads();
        for (int t = tid; t < 2048; t += 256) {
            int bb = t >> 7, dd = t & 127;
            ts[bb][dd] = g_t[(bb*NH + h)*DIMN + chd*128 + dd];
        }
        for (int t = tid; t < 4096; t += 256) {
            int dd = t >> 5, jj = t & 31;
            ws[dd][jj] = qkvw[(chd*128 + dd)*QLD + col + jj];
        }
        __syncthreads();
        #pragma unroll 8
        for (int dd = 0; dd < 128; dd++) {
            float wv = ws[dd][lane];
            a0 += ts[grp    ][dd] * wv;
            a1 += ts[grp + 8][dd] * wv;
        }
    }
    int ocol = h*HD + jb*32 + lane;
    float bias = qkvb[2*DIMN + ocol];
    g_ao[ grp     *DIMN + ocol] = a0 + bias;
    g_ao[(grp + 8)*DIMN + ocol] = a1 + bias;
}

// ---------------------------------------------------------------------------
// Kernel 6b: out[b, e] = ao[b,:] . proj_w[:, e] + proj_b[e]
// grid 64 (e-blocks of 32), block 256
__global__ void k_proj(const float* __restrict__ pw, const float* __restrict__ pb,
                       float* __restrict__ out) {
    int eb = blockIdx.x;
    int tid = threadIdx.x;
    int lane = tid & 31, grp = tid >> 5;
    __shared__ float as[16][128];
    __shared__ float ws[128][32];
    float a0 = 0.f, a1 = 0.f;
    for (int chd = 0; chd < 16; chd++) {
        __syncthreads();
        for (int t = tid; t < 2048; t += 256) {
            int bb = t >> 7, dd = t & 127;
            as[bb][dd] = g_ao[bb*DIMN + chd*128 + dd];
        }
        for (int t = tid; t < 4096; t += 256) {
            int dd = t >> 5, jj = t & 31;
            ws[dd][jj] = pw[(chd*128 + dd)*DIMN + eb*32 + jj];
        }
        __syncthreads();
        #pragma unroll 8
        for (int dd = 0; dd < 128; dd++) {
            float wv = ws[dd][lane];
            a0 += as[grp    ][dd] * wv;
            a1 += as[grp + 8][dd] * wv;
        }
    }
    int e = eb*32 + lane;
    float bias = pb[e];
    out[ grp     *DIMN + e] = a0 + bias;
    out[(grp + 8)*DIMN + e] = a1 + bias;
}

// ---------------------------------------------------------------------------
extern "C" void kernel_launch(void* const* d_in, const int* in_sizes, int n_in,
                              void* d_out, int out_size) {
    const float* x    = (const float*)d_in[0];
    const float* pos  = (const float*)d_in[1];
    const float* cls  = (const float*)d_in[2];
    const float* qkvw = (const float*)d_in[3];
    const float* qkvb = (const float*)d_in[4];
    const float* pw   = (const float*)d_in[5];
    const float* pb   = (const float*)d_in[6];
    float* out = (float*)d_out;

    k_q      <<<16, 128>>>(pos, cls, qkvw, qkvb);
    k_qhat   <<<dim3(256, 16), 256>>>(qkvw);
    k_scores <<<dim3(16, 16), 256>>>(x, pos, cls);
    k_softmax<<<256, 128>>>(qkvb);
    k_t      <<<dim3(8, 16), 256>>>(x, pos, cls);
    k_av     <<<dim3(4, 16), 256>>>(qkvw, qkvb);
    k_proj   <<<64, 256>>>(pw, pb, out);
}

// round 3
// speedup vs baseline: 1.3648x; 1.3648x over previous
#include <cuda_runtime.h>

// Problem constants
#define BB    16
#define CC    8
#define DD    511
#define DIMN  2048
#define SEQ   512
#define NH    16
#define HD    128
#define HWSZ  256
#define XB    (CC*DD*HWSZ)   // 1046528  (x batch stride)
#define XC    (DD*HWSZ)      // 130816   (x channel stride)
#define QLD   6144           // qkv_w leading dim (row length)
#define SCALE 0.08838834764831845f  // 128^-0.5

// Scratch (static device globals; no allocation anywhere)
__device__ float g_qp[16*DIMN];      // split-K partials for q
__device__ float g_q[DIMN];          // q for cls token (batch-independent)
__device__ float g_qhat[NH*DIMN];    // scale * Wk_h^T q_h
__device__ float g_sc[BB*NH*SEQ];    // scores -> probs (in place)
__device__ float g_t[BB*NH*DIMN];    // sum_s p * tok
__device__ float g_ao[BB*DIMN];      // attention output (pre-proj)

// ---------------------------------------------------------------------------
// Kernel 1a: split-K partial of q = tok0 @ Wq.
// grid (16 colblocks, 16 dchunks), block 128. Each block: 128 d-rows x 128 cols.
__global__ void k_q_part(const float* __restrict__ pos, const float* __restrict__ cls,
                         const float* __restrict__ qkvw) {
    __shared__ float t0[128];
    int dc = blockIdx.y;
    int tid = threadIdx.x;
    t0[tid] = cls[dc*128 + tid] + pos[dc*128 + tid];
    __syncthreads();
    int col = blockIdx.x * 128 + tid;
    const float* wp = qkvw + (dc*128)*QLD + col;
    float a0 = 0.f, a1 = 0.f, a2 = 0.f, a3 = 0.f;
    #pragma unroll 2
    for (int d = 0; d < 128; d += 8) {
        a0 += t0[d+0] * wp[(d+0)*QLD];
        a1 += t0[d+1] * wp[(d+1)*QLD];
        a2 += t0[d+2] * wp[(d+2)*QLD];
        a3 += t0[d+3] * wp[(d+3)*QLD];
        a0 += t0[d+4] * wp[(d+4)*QLD];
        a1 += t0[d+5] * wp[(d+5)*QLD];
        a2 += t0[d+6] * wp[(d+6)*QLD];
        a3 += t0[d+7] * wp[(d+7)*QLD];
    }
    g_qp[dc*DIMN + col] = (a0 + a1) + (a2 + a3);
}

// Kernel 1b: reduce the 16 partials (deterministic order) + bias.
// grid 16, block 128
__global__ void k_q_sum(const float* __restrict__ qkvb) {
    int col = blockIdx.x * 128 + threadIdx.x;
    float a = qkvb[col];
    #pragma unroll
    for (int dc = 0; dc < 16; dc++) a += g_qp[dc*DIMN + col];
    g_q[col] = a;
}

// ---------------------------------------------------------------------------
// Kernel 2: qhat[h, dim] = SCALE * sum_j qkv_w[dim, 2048 + h*128 + j] * q[h*128+j]
// grid (256, 16): 8 dims per CTA (warp each), block 256
__global__ void k_qhat(const float* __restrict__ qkvw) {
    int h = blockIdx.y;
    __shared__ float qv[HD];
    int tid = threadIdx.x;
    if (tid < HD) qv[tid] = g_q[h*HD + tid];
    __syncthreads();
    int w = tid >> 5, lane = tid & 31;
    int dim = blockIdx.x * 8 + w;
    const float* wr = qkvw + dim*QLD + DIMN + h*HD;
    float p = 0.f;
    #pragma unroll
    for (int j = lane; j < HD; j += 32) p += qv[j] * wr[j];
    #pragma unroll
    for (int o = 16; o; o >>= 1) p += __shfl_xor_sync(0xffffffffu, p, o);
    if (lane == 0) g_qhat[h*DIMN + dim] = p * SCALE;
}

// ---------------------------------------------------------------------------
// Kernel 3: scores[b,h,s] = qhat[h,:] . tok[b,s,:]  (tok built on the fly)
// grid (16 stiles, 16 b), block 256. Warp handles 4 tokens; lanes slice dims.
__global__ void k_scores(const float* __restrict__ x, const float* __restrict__ pos,
                         const float* __restrict__ cls) {
    int b = blockIdx.y;
    int tid = threadIdx.x, w = tid >> 5, lane = tid & 31;
    int s0 = blockIdx.x * 32 + w * 4;
    __shared__ float qh[NH * 512];

    float acc[NH][4];
    #pragma unroll
    for (int h = 0; h < NH; h++)
        #pragma unroll
        for (int j = 0; j < 4; j++) acc[h][j] = 0.f;

    for (int ch = 0; ch < 4; ch++) {
        for (int t = tid; t < NH*512; t += 256) {
            int h = t >> 9, dd = t & 511;
            qh[t] = g_qhat[h*DIMN + ch*512 + dd];
        }
        __syncthreads();
        #pragma unroll 2
        for (int it = 0; it < 16; it++) {
            int dd = it*32 + lane;
            int d  = ch*512 + dd;
            float tv[4];
            #pragma unroll
            for (int j = 0; j < 4; j++) {
                int s = s0 + j;
                float pv = pos[s*DIMN + d];
                float xv;
                if (s == 0) {
                    xv = cls[d];
                } else {
                    int c = d >> 8, r = d & 255;
                    xv = x[b*XB + c*XC + (s-1)*HWSZ + r];
                }
                tv[j] = xv + pv;
            }
            #pragma unroll
            for (int h = 0; h < NH; h++) {
                float qv = qh[h*512 + dd];
                #pragma unroll
                for (int j = 0; j < 4; j++) acc[h][j] += qv * tv[j];
            }
        }
        __syncthreads();
    }
    // butterfly reduce across the 32 lanes for all 64 outputs
    #pragma unroll
    for (int o = 16; o; o >>= 1) {
        #pragma unroll
        for (int h = 0; h < NH; h++)
            #pragma unroll
            for (int j = 0; j < 4; j++)
                acc[h][j] += __shfl_xor_sync(0xffffffffu, acc[h][j], o);
    }
    #pragma unroll
    for (int h = 0; h < NH; h++) {
        if (lane == h) {
            #pragma unroll
            for (int j = 0; j < 4; j++)
                g_sc[(b*NH + h)*SEQ + s0 + j] = acc[h][j];
        }
    }
}

// ---------------------------------------------------------------------------
// Kernel 4: softmax over s (512) per (b,h) row; adds the q.bk bias term.
// grid 256, block 128
__global__ void k_softmax(const float* __restrict__ qkvb) {
    int bh = blockIdx.x;
    int h = bh & 15;
    int tid = threadIdx.x;
    __shared__ float red[128];

    // sbias = SCALE * q_h . bk_h  (batch independent; zero here but kept general)
    red[tid] = g_q[h*HD + tid] * qkvb[DIMN + h*HD + tid];
    __syncthreads();
    for (int o = 64; o; o >>= 1) { if (tid < o) red[tid] += red[tid + o]; __syncthreads(); }
    float sbias = red[0] * SCALE;
    __syncthreads();

    float* row = g_sc + bh*SEQ;
    float v[4];
    float m = -1e30f;
    #pragma unroll
    for (int j = 0; j < 4; j++) { v[j] = row[tid + j*128] + sbias; m = fmaxf(m, v[j]); }
    red[tid] = m; __syncthreads();
    for (int o = 64; o; o >>= 1) { if (tid < o) red[tid] = fmaxf(red[tid], red[tid + o]); __syncthreads(); }
    m = red[0];
    __syncthreads();
    float s = 0.f;
    #pragma unroll
    for (int j = 0; j < 4; j++) { v[j] = expf(v[j] - m); s += v[j]; }
    red[tid] = s; __syncthreads();
    for (int o = 64; o; o >>= 1) { if (tid < o) red[tid] += red[tid + o]; __syncthreads(); }
    float inv = 1.f / red[0];
    #pragma unroll
    for (int j = 0; j < 4; j++) row[tid + j*128] = v[j] * inv;
}

// ---------------------------------------------------------------------------
// Kernel 5: t[b,h,dim] = sum_s p[b,h,s] * tok[b,s,dim]
// grid (16 dim-chunks, 16 b), block 128: thread owns one dim, all 16 heads in regs.
__global__ void k_t(const float* __restrict__ x, const float* __restrict__ pos,
                    const float* __restrict__ cls) {
    int b = blockIdx.y;
    int tid = threadIdx.x;
    int dim = blockIdx.x * 128 + tid;
    __shared__ float ps[NH*SEQ];  // 32 KB
    for (int t = tid; t < NH*SEQ; t += 128) ps[t] = g_sc[b*NH*SEQ + t];
    __syncthreads();

    int c = dim >> 8, r = dim & 255;
    const float* xp = x + b*XB + c*XC + r;   // token s>=1 -> xp[(s-1)*256]
    const float* pp = pos + dim;             // pp[s*DIMN]

    float acc[NH];
    #pragma unroll
    for (int h = 0; h < NH; h++) acc[h] = 0.f;

    // s = 0..3 (s=0 is cls token)
    {
        float tv0 = cls[dim] + pp[0];
        float tv1 = xp[0*HWSZ] + pp[1*DIMN];
        float tv2 = xp[1*HWSZ] + pp[2*DIMN];
        float tv3 = xp[2*HWSZ] + pp[3*DIMN];
        #pragma unroll
        for (int h = 0; h < NH; h++) {
            const float* pr = ps + h*SEQ;
            acc[h] += pr[0]*tv0 + pr[1]*tv1 + pr[2]*tv2 + pr[3]*tv3;
        }
    }
    for (int k = 1; k < 128; k++) {
        int s = k*4;
        float tv[4];
        #pragma unroll
        for (int j = 0; j < 4; j++)
            tv[j] = xp[(s + j - 1)*HWSZ] + pp[(s + j)*DIMN];
        #pragma unroll
        for (int h = 0; h < NH; h++) {
            float4 p4 = *reinterpret_cast<const float4*>(&ps[h*SEQ + s]);
            acc[h] += p4.x*tv[0] + p4.y*tv[1] + p4.z*tv[2] + p4.w*tv[3];
        }
    }
    #pragma unroll
    for (int h = 0; h < NH; h++)
        g_t[(b*NH + h)*DIMN + dim] = acc[h];
}

// ---------------------------------------------------------------------------
// Kernel 6a: ao[b, h*128 + j] = t[b,h,:] . Wv[:, 4096 + h*128 + j] + bv
// grid (4 jblocks, 16 h), block 256. smem-staged tiles; Wv read exactly once.
__global__ void k_av(const float* __restrict__ qkvw, const float* __restrict__ qkvb) {
    int h = blockIdx.y, jb = blockIdx.x;
    int tid = threadIdx.x;
    int lane = tid & 31, grp = tid >> 5;  // grp handles b = grp and grp+8
    __shared__ float ts[16][128];
    __shared__ float ws[128][32];
    int col = 2*DIMN + h*HD + jb*32;
    float a0 = 0.f, a1 = 0.f;
    for (int chd = 0; chd < 16; chd++) {
        __syncthreads();
        for (int t = tid; t < 2048; t += 256) {
            int bb = t >> 7, dd = t & 127;
            ts[bb][dd] = g_t[(bb*NH + h)*DIMN + chd*128 + dd];
        }
        for (int t = tid; t < 4096; t += 256) {
            int dd = t >> 5, jj = t & 31;
            ws[dd][jj] = qkvw[(chd*128 + dd)*QLD + col + jj];
        }
        __syncthreads();
        #pragma unroll 8
        for (int dd = 0; dd < 128; dd++) {
            float wv = ws[dd][lane];
            a0 += ts[grp    ][dd] * wv;
            a1 += ts[grp + 8][dd] * wv;
        }
    }
    int ocol = h*HD + jb*32 + lane;
    float bias = qkvb[2*DIMN + ocol];
    g_ao[ grp     *DIMN + ocol] = a0 + bias;
    g_ao[(grp + 8)*DIMN + ocol] = a1 + bias;
}

// ---------------------------------------------------------------------------
// Kernel 6b: out[b, e] = ao[b,:] . proj_w[:, e] + proj_b[e]
// grid 64 (e-blocks of 32), block 256
__global__ void k_proj(const float* __restrict__ pw, const float* __restrict__ pb,
                       float* __restrict__ out) {
    int eb = blockIdx.x;
    int tid = threadIdx.x;
    int lane = tid & 31, grp = tid >> 5;
    __shared__ float as[16][128];
    __shared__ float ws[128][32];
    float a0 = 0.f, a1 = 0.f;
    for (int chd = 0; chd < 16; chd++) {
        __syncthreads();
        for (int t = tid; t < 2048; t += 256) {
            int bb = t >> 7, dd = t & 127;
            as[bb][dd] = g_ao[bb*DIMN + chd*128 + dd];
        }
        for (int t = tid; t < 4096; t += 256) {
            int dd = t >> 5, jj = t & 31;
            ws[dd][jj] = pw[(chd*128 + dd)*DIMN + eb*32 + jj];
        }
        __syncthreads();
        #pragma unroll 8
        for (int dd = 0; dd < 128; dd++) {
            float wv = ws[dd][lane];
            a0 += as[grp    ][dd] * wv;
            a1 += as[grp + 8][dd] * wv;
        }
    }
    int e = eb*32 + lane;
    float bias = pb[e];
    out[ grp     *DIMN + e] = a0 + bias;
    out[(grp + 8)*DIMN + e] = a1 + bias;
}

// ---------------------------------------------------------------------------
extern "C" void kernel_launch(void* const* d_in, const int* in_sizes, int n_in,
                              void* d_out, int out_size) {
    const float* x    = (const float*)d_in[0];
    const float* pos  = (const float*)d_in[1];
    const float* cls  = (const float*)d_in[2];
    const float* qkvw = (const float*)d_in[3];
    const float* qkvb = (const float*)d_in[4];
    const float* pw   = (const float*)d_in[5];
    const float* pb   = (const float*)d_in[6];
    float* out = (float*)d_out;

    k_q_part <<<dim3(16, 16), 128>>>(pos, cls, qkvw);
    k_q_sum  <<<16, 128>>>(qkvb);
    k_qhat   <<<dim3(256, 16), 256>>>(qkvw);
    k_scores <<<dim3(16, 16), 256>>>(x, pos, cls);
    k_softmax<<<256, 128>>>(qkvb);
    k_t      <<<dim3(16, 16), 128>>>(x, pos, cls);
    k_av     <<<dim3(4, 16), 256>>>(qkvw, qkvb);
    k_proj   <<<64, 256>>>(pw, pb, out);
}

// round 4
// speedup vs baseline: 2.2165x; 1.6241x over previous
#include <cuda_runtime.h>

// Problem constants
#define BB    16
#define CC    8
#define DD    511
#define DIMN  2048
#define SEQ   512
#define NH    16
#define HD    128
#define HWSZ  256
#define XB    (CC*DD*HWSZ)   // 1046528  (x batch stride)
#define XC    (DD*HWSZ)      // 130816   (x channel stride)
#define QLD   6144           // qkv_w leading dim (row length)
#define SCALE 0.08838834764831845f  // 128^-0.5

// Scratch (static device globals; no allocation anywhere)
__device__ float g_qp[32*DIMN];        // split-K partials for q
__device__ float g_q[DIMN];            // q for cls token (batch-independent)
__device__ float g_qhat[NH*DIMN];      // scale * Wk_h^T q_h
__device__ float g_sc[BB*NH*SEQ];      // scores -> probs (in place)
__device__ float g_tp[4][BB*NH*DIMN];  // s-split partials of t = P @ tok
__device__ float g_aop[16][BB*DIMN];   // d-chunk partials of attn out @ Wv
__device__ float g_ao[BB*DIMN];        // attention output (pre-proj)
__device__ float g_outp[16][BB*DIMN];  // d-chunk partials of final proj

// ---------------------------------------------------------------------------
// Kernel 1a: split-K partial of q = tok0 @ Wq.
// grid (16 colblocks, 32 dchunks of 64 rows), block 128.
__global__ void k_q_part(const float* __restrict__ pos, const float* __restrict__ cls,
                         const float* __restrict__ qkvw) {
    __shared__ float t0[64];
    int dc = blockIdx.y;
    int tid = threadIdx.x;
    if (tid < 64) t0[tid] = cls[dc*64 + tid] + pos[dc*64 + tid];
    __syncthreads();
    int col = blockIdx.x * 128 + tid;
    const float* wp = qkvw + (dc*64)*QLD + col;
    float a0 = 0.f, a1 = 0.f, a2 = 0.f, a3 = 0.f;
    #pragma unroll 2
    for (int d = 0; d < 64; d += 8) {
        a0 += t0[d+0] * wp[(d+0)*QLD];
        a1 += t0[d+1] * wp[(d+1)*QLD];
        a2 += t0[d+2] * wp[(d+2)*QLD];
        a3 += t0[d+3] * wp[(d+3)*QLD];
        a0 += t0[d+4] * wp[(d+4)*QLD];
        a1 += t0[d+5] * wp[(d+5)*QLD];
        a2 += t0[d+6] * wp[(d+6)*QLD];
        a3 += t0[d+7] * wp[(d+7)*QLD];
    }
    g_qp[dc*DIMN + col] = (a0 + a1) + (a2 + a3);
}

// Kernel 1b: reduce the 32 partials (deterministic order) + bias. grid 16, block 128
__global__ void k_q_sum(const float* __restrict__ qkvb) {
    int col = blockIdx.x * 128 + threadIdx.x;
    float a = qkvb[col];
    #pragma unroll
    for (int dc = 0; dc < 32; dc++) a += g_qp[dc*DIMN + col];
    g_q[col] = a;
}

// ---------------------------------------------------------------------------
// Kernel 2: qhat[h, dim] = SCALE * sum_j qkv_w[dim, 2048 + h*128 + j] * q[h*128+j]
// grid (256, 16): 8 dims per CTA (warp each), block 256
__global__ void k_qhat(const float* __restrict__ qkvw) {
    int h = blockIdx.y;
    __shared__ float qv[HD];
    int tid = threadIdx.x;
    if (tid < HD) qv[tid] = g_q[h*HD + tid];
    __syncthreads();
    int w = tid >> 5, lane = tid & 31;
    int dim = blockIdx.x * 8 + w;
    const float* wr = qkvw + dim*QLD + DIMN + h*HD;
    float p = 0.f;
    #pragma unroll
    for (int j = lane; j < HD; j += 32) p += qv[j] * wr[j];
    #pragma unroll
    for (int o = 16; o; o >>= 1) p += __shfl_xor_sync(0xffffffffu, p, o);
    if (lane == 0) g_qhat[h*DIMN + dim] = p * SCALE;
}

// ---------------------------------------------------------------------------
// Kernel 3: scores[b,h,s] = qhat[h,:] . tok[b,s,:]  (tok built on the fly)
// grid (16 stiles, 16 b), block 512 (16 warps). Warp handles 2 tokens.
__global__ void k_scores(const float* __restrict__ x, const float* __restrict__ pos,
                         const float* __restrict__ cls) {
    int b = blockIdx.y;
    int tid = threadIdx.x, w = tid >> 5, lane = tid & 31;
    int s0 = blockIdx.x * 32 + w * 2;
    __shared__ float qh[NH * 512];

    float acc[NH][2];
    #pragma unroll
    for (int h = 0; h < NH; h++) { acc[h][0] = 0.f; acc[h][1] = 0.f; }

    for (int ch = 0; ch < 4; ch++) {
        for (int t = tid; t < NH*512; t += 512) {
            int h = t >> 9, dd = t & 511;
            qh[t] = g_qhat[h*DIMN + ch*512 + dd];
        }
        __syncthreads();
        #pragma unroll 4
        for (int it = 0; it < 16; it++) {
            int dd = it*32 + lane;
            int d  = ch*512 + dd;
            float tv[2];
            #pragma unroll
            for (int j = 0; j < 2; j++) {
                int s = s0 + j;
                float pv = pos[s*DIMN + d];
                float xv;
                if (s == 0) {
                    xv = cls[d];
                } else {
                    int c = d >> 8, r = d & 255;
                    xv = x[b*XB + c*XC + (s-1)*HWSZ + r];
                }
                tv[j] = xv + pv;
            }
            #pragma unroll
            for (int h = 0; h < NH; h++) {
                float qv = qh[h*512 + dd];
                acc[h][0] += qv * tv[0];
                acc[h][1] += qv * tv[1];
            }
        }
        __syncthreads();
    }
    // butterfly reduce across lanes (32 outputs per warp)
    #pragma unroll
    for (int o = 16; o; o >>= 1) {
        #pragma unroll
        for (int h = 0; h < NH; h++) {
            acc[h][0] += __shfl_xor_sync(0xffffffffu, acc[h][0], o);
            acc[h][1] += __shfl_xor_sync(0xffffffffu, acc[h][1], o);
        }
    }
    #pragma unroll
    for (int h = 0; h < NH; h++) {
        #pragma unroll
        for (int j = 0; j < 2; j++) {
            if (lane == h*2 + j)
                g_sc[(b*NH + h)*SEQ + s0 + j] = acc[h][j];
        }
    }
}

// ---------------------------------------------------------------------------
// Kernel 4: softmax over s (512) per (b,h) row; adds the q.bk bias term.
// grid 256, block 128
__global__ void k_softmax(const float* __restrict__ qkvb) {
    int bh = blockIdx.x;
    int h = bh & 15;
    int tid = threadIdx.x;
    __shared__ float red[128];

    red[tid] = g_q[h*HD + tid] * qkvb[DIMN + h*HD + tid];
    __syncthreads();
    for (int o = 64; o; o >>= 1) { if (tid < o) red[tid] += red[tid + o]; __syncthreads(); }
    float sbias = red[0] * SCALE;
    __syncthreads();

    float* row = g_sc + bh*SEQ;
    float v[4];
    float m = -1e30f;
    #pragma unroll
    for (int j = 0; j < 4; j++) { v[j] = row[tid + j*128] + sbias; m = fmaxf(m, v[j]); }
    red[tid] = m; __syncthreads();
    for (int o = 64; o; o >>= 1) { if (tid < o) red[tid] = fmaxf(red[tid], red[tid + o]); __syncthreads(); }
    m = red[0];
    __syncthreads();
    float s = 0.f;
    #pragma unroll
    for (int j = 0; j < 4; j++) { v[j] = expf(v[j] - m); s += v[j]; }
    red[tid] = s; __syncthreads();
    for (int o = 64; o; o >>= 1) { if (tid < o) red[tid] += red[tid + o]; __syncthreads(); }
    float inv = 1.f / red[0];
    #pragma unroll
    for (int j = 0; j < 4; j++) row[tid + j*128] = v[j] * inv;
}

// ---------------------------------------------------------------------------
// Kernel 5: t partials: g_tp[sq][b,h,dim] = sum_{s in quarter sq} p[b,h,s]*tok[b,s,dim]
// grid (8 dim-chunks, 16 b, 4 s-quarters), block 256.
__global__ void k_t(const float* __restrict__ x, const float* __restrict__ pos,
                    const float* __restrict__ cls) {
    int b = blockIdx.y, sq = blockIdx.z;
    int tid = threadIdx.x;
    int dim = blockIdx.x * 256 + tid;
    int sbase = sq * 128;
    __shared__ float ps[NH*128];  // 8 KB: this quarter's probs
    for (int t = tid; t < NH*128; t += 256) {
        int h = t >> 7, ss = t & 127;
        ps[t] = g_sc[(b*NH + h)*SEQ + sbase + ss];
    }
    __syncthreads();

    int c = dim >> 8, r = dim & 255;
    const float* xp = x + b*XB + c*XC + r;   // token s>=1 -> xp[(s-1)*256]
    const float* pp = pos + dim;             // pp[s*DIMN]

    float acc[NH];
    #pragma unroll
    for (int h = 0; h < NH; h++) acc[h] = 0.f;

    int kstart = 0;
    if (sq == 0) {
        // s = 0..3 (s=0 is cls token)
        float tv0 = cls[dim] + pp[0];
        float tv1 = xp[0*HWSZ] + pp[1*DIMN];
        float tv2 = xp[1*HWSZ] + pp[2*DIMN];
        float tv3 = xp[2*HWSZ] + pp[3*DIMN];
        #pragma unroll
        for (int h = 0; h < NH; h++) {
            const float* pr = ps + h*128;
            acc[h] += pr[0]*tv0 + pr[1]*tv1 + pr[2]*tv2 + pr[3]*tv3;
        }
        kstart = 1;
    }
    for (int k = kstart; k < 32; k++) {
        int s = sbase + k*4;
        float tv[4];
        #pragma unroll
        for (int j = 0; j < 4; j++)
            tv[j] = xp[(s + j - 1)*HWSZ] + pp[(s + j)*DIMN];
        #pragma unroll
        for (int h = 0; h < NH; h++) {
            float4 p4 = *reinterpret_cast<const float4*>(&ps[h*128 + k*4]);
            acc[h] += p4.x*tv[0] + p4.y*tv[1] + p4.z*tv[2] + p4.w*tv[3];
        }
    }
    #pragma unroll
    for (int h = 0; h < NH; h++)
        g_tp[sq][(b*NH + h)*DIMN + dim] = acc[h];
}

// ---------------------------------------------------------------------------
// Kernel 6a: partial ao over one d-chunk:
//   g_aop[chd][b, h*128+j] = t[b,h, chd*128:+128] . Wv[chd rows, col block]
// grid (4 jblocks, 16 h, 16 chd), block 256.
__global__ void k_avp(const float* __restrict__ qkvw) {
    int h = blockIdx.y, jb = blockIdx.x, chd = blockIdx.z;
    int tid = threadIdx.x;
    int lane = tid & 31, grp = tid >> 5;  // grp handles b = grp and grp+8
    __shared__ float ts[16][128];
    __shared__ float ws[128][32];
    int col = 2*DIMN + h*HD + jb*32;
    for (int t = tid; t < 2048; t += 256) {
        int bb = t >> 7, dd = t & 127;
        int idx = (bb*NH + h)*DIMN + chd*128 + dd;
        ts[bb][dd] = ((g_tp[0][idx] + g_tp[1][idx]) + (g_tp[2][idx] + g_tp[3][idx]));
    }
    for (int t = tid; t < 4096; t += 256) {
        int dd = t >> 5, jj = t & 31;
        ws[dd][jj] = qkvw[(chd*128 + dd)*QLD + col + jj];
    }
    __syncthreads();
    float a0 = 0.f, a1 = 0.f;
    #pragma unroll 8
    for (int dd = 0; dd < 128; dd++) {
        float wv = ws[dd][lane];
        a0 += ts[grp    ][dd] * wv;
        a1 += ts[grp + 8][dd] * wv;
    }
    int ocol = h*HD + jb*32 + lane;
    g_aop[chd][ grp     *DIMN + ocol] = a0;
    g_aop[chd][(grp + 8)*DIMN + ocol] = a1;
}

// Kernel 6b: reduce 16 chunk partials + bias -> g_ao. grid 128, block 256.
__global__ void k_ao_sum(const float* __restrict__ qkvb) {
    int idx = blockIdx.x * 256 + threadIdx.x;   // 0 .. 32767
    int col = idx & (DIMN-1);
    float a = qkvb[2*DIMN + col];
    #pragma unroll
    for (int c = 0; c < 16; c++) a += g_aop[c][idx];
    g_ao[idx] = a;
}

// ---------------------------------------------------------------------------
// Kernel 7a: partial proj over one d-chunk.
// grid (64 eblocks, 16 chd), block 256.
__global__ void k_projp(const float* __restrict__ pw) {
    int eb = blockIdx.x, chd = blockIdx.y;
    int tid = threadIdx.x;
    int lane = tid & 31, grp = tid >> 5;
    __shared__ float as[16][128];
    __shared__ float ws[128][32];
    for (int t = tid; t < 2048; t += 256) {
        int bb = t >> 7, dd = t & 127;
        as[bb][dd] = g_ao[bb*DIMN + chd*128 + dd];
    }
    for (int t = tid; t < 4096; t += 256) {
        int dd = t >> 5, jj = t & 31;
        ws[dd][jj] = pw[(chd*128 + dd)*DIMN + eb*32 + jj];
    }
    __syncthreads();
    float a0 = 0.f, a1 = 0.f;
    #pragma unroll 8
    for (int dd = 0; dd < 128; dd++) {
        float wv = ws[dd][lane];
        a0 += as[grp    ][dd] * wv;
        a1 += as[grp + 8][dd] * wv;
    }
    int e = eb*32 + lane;
    g_outp[chd][ grp     *DIMN + e] = a0;
    g_outp[chd][(grp + 8)*DIMN + e] = a1;
}

// Kernel 7b: reduce 16 chunk partials + bias -> out. grid 128, block 256.
__global__ void k_out_sum(const float* __restrict__ pb, float* __restrict__ out) {
    int idx = blockIdx.x * 256 + threadIdx.x;
    int e = idx & (DIMN-1);
    float a = pb[e];
    #pragma unroll
    for (int c = 0; c < 16; c++) a += g_outp[c][idx];
    out[idx] = a;
}

// ---------------------------------------------------------------------------
extern "C" void kernel_launch(void* const* d_in, const int* in_sizes, int n_in,
                              void* d_out, int out_size) {
    const float* x    = (const float*)d_in[0];
    const float* pos  = (const float*)d_in[1];
    const float* cls  = (const float*)d_in[2];
    const float* qkvw = (const float*)d_in[3];
    const float* qkvb = (const float*)d_in[4];
    const float* pw   = (const float*)d_in[5];
    const float* pb   = (const float*)d_in[6];
    float* out = (float*)d_out;

    k_q_part <<<dim3(16, 32), 128>>>(pos, cls, qkvw);
    k_q_sum  <<<16, 128>>>(qkvb);
    k_qhat   <<<dim3(256, 16), 256>>>(qkvw);
    k_scores <<<dim3(16, 16), 512>>>(x, pos, cls);
    k_softmax<<<256, 128>>>(qkvb);
    k_t      <<<dim3(8, 16, 4), 256>>>(x, pos, cls);
    k_avp    <<<dim3(4, 16, 16), 256>>>(qkvw);
    k_ao_sum <<<128, 256>>>(qkvb);
    k_projp  <<<dim3(64, 16), 256>>>(pw);
    k_out_sum<<<128, 256>>>(pb, out);
}

// round 9
// speedup vs baseline: 2.5262x; 1.1397x over previous
#include <cuda_runtime.h>

// Problem constants
#define BB    16
#define CC    8
#define DD    511
#define DIMN  2048
#define SEQ   512
#define NH    16
#define HD    128
#define HWSZ  256
#define XB    (CC*DD*HWSZ)   // 1046528  (x batch stride)
#define XC    (DD*HWSZ)      // 130816   (x channel stride)
#define QLD   6144           // qkv_w leading dim (row length)
#define SCALE 0.08838834764831845f  // 128^-0.5

// Scratch (static device globals; no allocation anywhere)
__device__ float g_qp[32*DIMN];        // split-K partials for q
__device__ float g_q[DIMN];            // q for cls token (batch-independent)
__device__ float g_qhat[NH*DIMN];      // scale * Wk_h^T q_h
__device__ float g_sc[BB*NH*SEQ];      // scores -> probs (in place)
__device__ float g_tp[8][BB*NH*DIMN];  // s-split partials of t = P @ tok
__device__ float g_t[BB*NH*DIMN];      // t = P @ tok
__device__ float g_aop[16][BB*DIMN];   // d-chunk partials of attn out @ Wv
__device__ float g_ao[BB*DIMN];        // attention output (pre-proj)
__device__ float g_outp[16][BB*DIMN];  // d-chunk partials of final proj

// ---------------------------------------------------------------------------
// Kernel 1a: split-K partial of q = tok0 @ Wq.
// grid (16 colblocks, 32 dchunks of 64 rows), block 128.
__global__ void k_q_part(const float* __restrict__ pos, const float* __restrict__ cls,
                         const float* __restrict__ qkvw) {
    __shared__ float t0[64];
    int dc = blockIdx.y;
    int tid = threadIdx.x;
    if (tid < 64) t0[tid] = cls[dc*64 + tid] + pos[dc*64 + tid];
    __syncthreads();
    int col = blockIdx.x * 128 + tid;
    const float* wp = qkvw + (dc*64)*QLD + col;
    float a0 = 0.f, a1 = 0.f, a2 = 0.f, a3 = 0.f;
    #pragma unroll 2
    for (int d = 0; d < 64; d += 8) {
        a0 += t0[d+0] * wp[(d+0)*QLD];
        a1 += t0[d+1] * wp[(d+1)*QLD];
        a2 += t0[d+2] * wp[(d+2)*QLD];
        a3 += t0[d+3] * wp[(d+3)*QLD];
        a0 += t0[d+4] * wp[(d+4)*QLD];
        a1 += t0[d+5] * wp[(d+5)*QLD];
        a2 += t0[d+6] * wp[(d+6)*QLD];
        a3 += t0[d+7] * wp[(d+7)*QLD];
    }
    g_qp[dc*DIMN + col] = (a0 + a1) + (a2 + a3);
}

// Kernel 1b: reduce the 32 partials (deterministic order) + bias. grid 16, block 128
__global__ void k_q_sum(const float* __restrict__ qkvb) {
    int col = blockIdx.x * 128 + threadIdx.x;
    float a = qkvb[col];
    #pragma unroll
    for (int dc = 0; dc < 32; dc++) a += g_qp[dc*DIMN + col];
    g_q[col] = a;
}

// ---------------------------------------------------------------------------
// Kernel 2: qhat[h, dim] = SCALE * sum_j qkv_w[dim, 2048 + h*128 + j] * q[h*128+j]
// grid (256, 16): 8 dims per CTA (one per warp), block 256, float4 loads.
__global__ void k_qhat(const float* __restrict__ qkvw) {
    int h = blockIdx.y;
    __shared__ float4 qv4[32];
    int tid = threadIdx.x;
    if (tid < 32) qv4[tid] = *reinterpret_cast<const float4*>(&g_q[h*HD + tid*4]);
    __syncthreads();
    int w = tid >> 5, lane = tid & 31;
    int dim = blockIdx.x * 8 + w;
    const float4* wr4 = reinterpret_cast<const float4*>(qkvw + dim*QLD + DIMN + h*HD);
    float4 wv = wr4[lane];
    float4 qv = qv4[lane];
    float p = wv.x*qv.x + wv.y*qv.y + wv.z*qv.z + wv.w*qv.w;
    #pragma unroll
    for (int o = 16; o; o >>= 1) p += __shfl_xor_sync(0xffffffffu, p, o);
    if (lane == 0) g_qhat[h*DIMN + dim] = p * SCALE;
}

// ---------------------------------------------------------------------------
// Kernel 3: scores[b,h,s] = qhat[h,:] . tok[b,s,:]  (tok built on the fly)
// grid (32 stiles, 16 b), block 256 (8 warps). Warp = 4 tokens x 8 heads.
// Lane owns 4 consecutive dims (float4).
__global__ void __launch_bounds__(256, 3)
k_scores(const float* __restrict__ x, const float* __restrict__ pos,
         const float* __restrict__ cls) {
    int b = blockIdx.y;
    int tid = threadIdx.x, w = tid >> 5, lane = tid & 31;
    int tg = w >> 1;            // token group 0..3
    int hh = (w & 1) * 8;       // head base: 0 or 8
    int s0 = blockIdx.x * 16 + tg * 4;
    __shared__ float qh[NH * 512];   // 32 KB, this d-chunk, all heads

    float acc[8][4];
    #pragma unroll
    for (int h = 0; h < 8; h++)
        #pragma unroll
        for (int j = 0; j < 4; j++) acc[h][j] = 0.f;

    for (int ch = 0; ch < 4; ch++) {
        // stage qhat chunk (float4)
        for (int t4 = tid; t4 < NH*128; t4 += 256) {
            int h = t4 >> 7, dd4 = t4 & 127;
            *reinterpret_cast<float4*>(&qh[h*512 + dd4*4]) =
                *reinterpret_cast<const float4*>(&g_qhat[h*DIMN + ch*512 + dd4*4]);
        }
        __syncthreads();
        #pragma unroll
        for (int it = 0; it < 4; it++) {
            int dd = it*128 + lane*4;     // within chunk
            int d  = ch*512 + dd;         // absolute dim
            int c = d >> 8, r = d & 255;  // all 4 dims in same channel
            float4 tv[4];
            #pragma unroll
            for (int j = 0; j < 4; j++) {
                int s = s0 + j;
                float4 pv = *reinterpret_cast<const float4*>(&pos[s*DIMN + d]);
                float4 xv;
                if (s == 0) {
                    xv = *reinterpret_cast<const float4*>(&cls[d]);
                } else {
                    xv = *reinterpret_cast<const float4*>(&x[b*XB + c*XC + (s-1)*HWSZ + r]);
                }
                tv[j].x = xv.x + pv.x; tv[j].y = xv.y + pv.y;
                tv[j].z = xv.z + pv.z; tv[j].w = xv.w + pv.w;
            }
            #pragma unroll
            for (int h = 0; h < 8; h++) {
                float4 qv = *reinterpret_cast<const float4*>(&qh[(hh + h)*512 + dd]);
                #pragma unroll
                for (int j = 0; j < 4; j++) {
                    acc[h][j] += qv.x*tv[j].x + qv.y*tv[j].y
                               + qv.z*tv[j].z + qv.w*tv[j].w;
                }
            }
        }
        __syncthreads();
    }
    // butterfly reduce (32 outputs per warp)
    #pragma unroll
    for (int o = 16; o; o >>= 1)
        #pragma unroll
        for (int h = 0; h < 8; h++)
            #pragma unroll
            for (int j = 0; j < 4; j++)
                acc[h][j] += __shfl_xor_sync(0xffffffffu, acc[h][j], o);
    // lane (h*4+j) writes its output
    float outv = 0.f;
    #pragma unroll
    for (int h = 0; h < 8; h++)
        #pragma unroll
        for (int j = 0; j < 4; j++)
            if (lane == h*4 + j) outv = acc[h][j];
    int h8 = lane >> 2, j = lane & 3;
    g_sc[(b*NH + hh + h8)*SEQ + s0 + j] = outv;
}

// ---------------------------------------------------------------------------
// Kernel 4: softmax over s (512) per (b,h) row; adds the q.bk bias term.
// grid 256, block 128
__global__ void k_softmax(const float* __restrict__ qkvb) {
    int bh = blockIdx.x;
    int h = bh & 15;
    int tid = threadIdx.x;
    __shared__ float red[128];

    red[tid] = g_q[h*HD + tid] * qkvb[DIMN + h*HD + tid];
    __syncthreads();
    for (int o = 64; o; o >>= 1) { if (tid < o) red[tid] += red[tid + o]; __syncthreads(); }
    float sbias = red[0] * SCALE;
    __syncthreads();

    float* row = g_sc + bh*SEQ;
    float v[4];
    float m = -1e30f;
    #pragma unroll
    for (int j = 0; j < 4; j++) { v[j] = row[tid + j*128] + sbias; m = fmaxf(m, v[j]); }
    red[tid] = m; __syncthreads();
    for (int o = 64; o; o >>= 1) { if (tid < o) red[tid] = fmaxf(red[tid], red[tid + o]); __syncthreads(); }
    m = red[0];
    __syncthreads();
    float s = 0.f;
    #pragma unroll
    for (int j = 0; j < 4; j++) { v[j] = expf(v[j] - m); s += v[j]; }
    red[tid] = s; __syncthreads();
    for (int o = 64; o; o >>= 1) { if (tid < o) red[tid] += red[tid + o]; __syncthreads(); }
    float inv = 1.f / red[0];
    #pragma unroll
    for (int j = 0; j < 4; j++) row[tid + j*128] = v[j] * inv;
}

// ---------------------------------------------------------------------------
// Kernel 5: t partials: g_tp[sq][b,h,dim] over s in [sq*64, sq*64+64).
// grid (4 dchunks, 16 b, 8 sq), block 256. Warp = 128 dims x 8 heads; lane = 4 dims.
__global__ void __launch_bounds__(256, 3)
k_t(const float* __restrict__ x, const float* __restrict__ pos,
    const float* __restrict__ cls) {
    int b = blockIdx.y, sq = blockIdx.z;
    int tid = threadIdx.x, w = tid >> 5, lane = tid & 31;
    int dg = w >> 1;            // dim group 0..3
    int hh = (w & 1) * 8;       // head base
    int dim = blockIdx.x*512 + dg*128 + lane*4;
    int sbase = sq * 64;
    __shared__ float ps[NH][64];  // 4 KB
    for (int t = tid; t < NH*64; t += 256) {
        int h = t >> 6, ss = t & 63;
        ps[h][ss] = g_sc[(b*NH + h)*SEQ + sbase + ss];
    }
    __syncthreads();

    int c = dim >> 8, r = dim & 255;          // 4 dims share channel c
    const float* xp = x + b*XB + c*XC + r;    // token s>=1 -> xp + (s-1)*HWSZ
    const float* pp = pos + dim;

    float4 acc[8];
    #pragma unroll
    for (int h = 0; h < 8; h++) acc[h] = make_float4(0.f, 0.f, 0.f, 0.f);

    int k0 = 0;
    if (sq == 0) {
        // k = 0: s = 0..3, s=0 is cls
        float4 tv[4];
        {
            float4 cv = *reinterpret_cast<const float4*>(&cls[dim]);
            float4 pv = *reinterpret_cast<const float4*>(pp);
            tv[0].x = cv.x+pv.x; tv[0].y = cv.y+pv.y; tv[0].z = cv.z+pv.z; tv[0].w = cv.w+pv.w;
        }
        #pragma unroll
        for (int j = 1; j < 4; j++) {
            float4 xv = *reinterpret_cast<const float4*>(&xp[(j-1)*HWSZ]);
            float4 pv = *reinterpret_cast<const float4*>(&pp[j*DIMN]);
            tv[j].x = xv.x+pv.x; tv[j].y = xv.y+pv.y; tv[j].z = xv.z+pv.z; tv[j].w = xv.w+pv.w;
        }
        #pragma unroll
        for (int h = 0; h < 8; h++) {
            float4 p4 = *reinterpret_cast<const float4*>(&ps[hh + h][0]);
            acc[h].x += p4.x*tv[0].x + p4.y*tv[1].x + p4.z*tv[2].x + p4.w*tv[3].x;
            acc[h].y += p4.x*tv[0].y + p4.y*tv[1].y + p4.z*tv[2].y + p4.w*tv[3].y;
            acc[h].z += p4.x*tv[0].z + p4.y*tv[1].z + p4.z*tv[2].z + p4.w*tv[3].z;
            acc[h].w += p4.x*tv[0].w + p4.y*tv[1].w + p4.z*tv[2].w + p4.w*tv[3].w;
        }
        k0 = 1;
    }
    for (int k = k0; k < 16; k++) {
        int s = sbase + k*4;
        float4 tv[4];
        #pragma unroll
        for (int j = 0; j < 4; j++) {
            float4 xv = *reinterpret_cast<const float4*>(&xp[(s + j - 1)*HWSZ]);
            float4 pv = *reinterpret_cast<const float4*>(&pp[(s + j)*(long)DIMN]);
            tv[j].x = xv.x+pv.x; tv[j].y = xv.y+pv.y; tv[j].z = xv.z+pv.z; tv[j].w = xv.w+pv.w;
        }
        #pragma unroll
        for (int h = 0; h < 8; h++) {
            float4 p4 = *reinterpret_cast<const float4*>(&ps[hh + h][k*4]);
            acc[h].x += p4.x*tv[0].x + p4.y*tv[1].x + p4.z*tv[2].x + p4.w*tv[3].x;
            acc[h].y += p4.x*tv[0].y + p4.y*tv[1].y + p4.z*tv[2].y + p4.w*tv[3].y;
            acc[h].z += p4.x*tv[0].z + p4.y*tv[1].z + p4.z*tv[2].z + p4.w*tv[3].z;
            acc[h].w += p4.x*tv[0].w + p4.y*tv[1].w + p4.z*tv[2].w + p4.w*tv[3].w;
        }
    }
    #pragma unroll
    for (int h = 0; h < 8; h++)
        *reinterpret_cast<float4*>(&g_tp[sq][(b*NH + hh + h)*DIMN + dim]) = acc[h];
}

// Kernel 5b: collapse the 8 s-partials (deterministic order). grid 512, block 256.
__global__ void k_t_sum() {
    int i4 = blockIdx.x * 256 + threadIdx.x;   // float4 index, 131072 total
    float4 a = make_float4(0.f, 0.f, 0.f, 0.f);
    #pragma unroll
    for (int sq = 0; sq < 8; sq++) {
        float4 v = *reinterpret_cast<const float4*>(&g_tp[sq][i4*4]);
        a.x += v.x; a.y += v.y; a.z += v.z; a.w += v.w;
    }
    *reinterpret_cast<float4*>(&g_t[i4*4]) = a;
}

// ---------------------------------------------------------------------------
// Kernel 6a: partial ao over one d-chunk.
// grid (4 jblocks, 16 h, 16 chd), block 256.
__global__ void k_avp(const float* __restrict__ qkvw) {
    int h = blockIdx.y, jb = blockIdx.x, chd = blockIdx.z;
    int tid = threadIdx.x;
    int lane = tid & 31, grp = tid >> 5;  // grp handles b = grp and grp+8
    __shared__ float ts[16][128];
    __shared__ float ws[128][32];
    int col = 2*DIMN + h*HD + jb*32;
    for (int t = tid; t < 2048; t += 256) {
        int bb = t >> 7, dd = t & 127;
        ts[bb][dd] = g_t[(bb*NH + h)*DIMN + chd*128 + dd];
    }
    for (int t = tid; t < 4096; t += 256) {
        int dd = t >> 5, jj = t & 31;
        ws[dd][jj] = qkvw[(chd*128 + dd)*QLD + col + jj];
    }
    __syncthreads();
    float a0 = 0.f, a1 = 0.f;
    #pragma unroll 8
    for (int dd = 0; dd < 128; dd++) {
        float wv = ws[dd][lane];
        a0 += ts[grp    ][dd] * wv;
        a1 += ts[grp + 8][dd] * wv;
    }
    int ocol = h*HD + jb*32 + lane;
    g_aop[chd][ grp     *DIMN + ocol] = a0;
    g_aop[chd][(grp + 8)*DIMN + ocol] = a1;
}

// Kernel 6b: reduce 16 chunk partials + bias -> g_ao. grid 128, block 256.
__global__ void k_ao_sum(const float* __restrict__ qkvb) {
    int idx = blockIdx.x * 256 + threadIdx.x;   // 0 .. 32767
    int col = idx & (DIMN-1);
    float a = qkvb[2*DIMN + col];
    #pragma unroll
    for (int c = 0; c < 16; c++) a += g_aop[c][idx];
    g_ao[idx] = a;
}

// ---------------------------------------------------------------------------
// Kernel 7a: partial proj over one d-chunk. grid (64 eblocks, 16 chd), block 256.
__global__ void k_projp(const float* __restrict__ pw) {
    int eb = blockIdx.x, chd = blockIdx.y;
    int tid = threadIdx.x;
    int lane = tid & 31, grp = tid >> 5;
    __shared__ float as[16][128];
    __shared__ float ws[128][32];
    for (int t = tid; t < 2048; t += 256) {
        int bb = t >> 7, dd = t & 127;
        as[bb][dd] = g_ao[bb*DIMN + chd*128 + dd];
    }
    for (int t = tid; t < 4096; t += 256) {
        int dd = t >> 5, jj = t & 31;
        ws[dd][jj] = pw[(chd*128 + dd)*DIMN + eb*32 + jj];
    }
    __syncthreads();
    float a0 = 0.f, a1 = 0.f;
    #pragma unroll 8
    for (int dd = 0; dd < 128; dd++) {
        float wv = ws[dd][lane];
        a0 += as[grp    ][dd] * wv;
        a1 += as[grp + 8][dd] * wv;
    }
    int e = eb*32 + lane;
    g_outp[chd][ grp     *DIMN + e] = a0;
    g_outp[chd][(grp + 8)*DIMN + e] = a1;
}

// Kernel 7b: reduce 16 chunk partials + bias -> out. grid 128, block 256.
__global__ void k_out_sum(const float* __restrict__ pb, float* __restrict__ out) {
    int idx = blockIdx.x * 256 + threadIdx.x;
    int e = idx & (DIMN-1);
    float a = pb[e];
    #pragma unroll
    for (int c = 0; c < 16; c++) a += g_outp[c][idx];
    out[idx] = a;
}

// ---------------------------------------------------------------------------
extern "C" void kernel_launch(void* const* d_in, const int* in_sizes, int n_in,
                              void* d_out, int out_size) {
    const float* x    = (const float*)d_in[0];
    const float* pos  = (const float*)d_in[1];
    const float* cls  = (const float*)d_in[2];
    const float* qkvw = (const float*)d_in[3];
    const float* qkvb = (const float*)d_in[4];
    const float* pw   = (const float*)d_in[5];
    const float* pb   = (const float*)d_in[6];
    float* out = (float*)d_out;

    k_q_part <<<dim3(16, 32), 128>>>(pos, cls, qkvw);
    k_q_sum  <<<16, 128>>>(qkvb);
    k_qhat   <<<dim3(256, 16), 256>>>(qkvw);
    k_scores <<<dim3(32, 16), 256>>>(x, pos, cls);
    k_softmax<<<256, 128>>>(qkvb);
    k_t      <<<dim3(4, 16, 8), 256>>>(x, pos, cls);
    k_t_sum  <<<512, 256>>>();
    k_avp    <<<dim3(4, 16, 16), 256>>>(qkvw);
    k_ao_sum <<<128, 256>>>(qkvb);
    k_projp  <<<dim3(64, 16), 256>>>(pw);
    k_out_sum<<<128, 256>>>(pb, out);
}

// round 11
// speedup vs baseline: 3.0043x; 1.1893x over previous
#include <cuda_runtime.h>

// Problem constants
#define BB    16
#define CC    8
#define DD    511
#define DIMN  2048
#define SEQ   512
#define NH    16
#define HD    128
#define HWSZ  256
#define XB    (CC*DD*HWSZ)   // 1046528  (x batch stride)
#define XC    (DD*HWSZ)      // 130816   (x channel stride)
#define QLD   6144           // qkv_w leading dim (row length)
#define SCALE 0.08838834764831845f  // 128^-0.5

// Scratch (static device globals; no allocation anywhere)
__device__ float g_qp[32*DIMN];        // split-K partials for q
__device__ float g_q[DIMN];            // q for cls token (batch-independent)
__device__ float g_qhat[NH*DIMN];      // scale * Wk_h^T q_h
__device__ float g_sc[BB*NH*SEQ];      // scores -> probs (in place)
__device__ float g_tp[4][BB*NH*DIMN];  // s-split partials of t = P @ tok
__device__ float g_t[BB*NH*DIMN];      // t = P @ tok
__device__ float g_aop[16][BB*DIMN];   // d-chunk partials of attn out @ Wv
__device__ float g_ao[BB*DIMN];        // attention output (pre-proj)
__device__ float g_outp[16][BB*DIMN];  // d-chunk partials of final proj

// ---------------------------------------------------------------------------
// Kernel 1a: split-K partial of q = tok0 @ Wq.
// grid (16 colblocks, 32 dchunks of 64 rows), block 128.
__global__ void k_q_part(const float* __restrict__ pos, const float* __restrict__ cls,
                         const float* __restrict__ qkvw) {
    __shared__ float t0[64];
    int dc = blockIdx.y;
    int tid = threadIdx.x;
    if (tid < 64) t0[tid] = cls[dc*64 + tid] + pos[dc*64 + tid];
    __syncthreads();
    int col = blockIdx.x * 128 + tid;
    const float* wp = qkvw + (dc*64)*QLD + col;
    float a0 = 0.f, a1 = 0.f, a2 = 0.f, a3 = 0.f;
    #pragma unroll 2
    for (int d = 0; d < 64; d += 8) {
        a0 += t0[d+0] * wp[(d+0)*QLD];
        a1 += t0[d+1] * wp[(d+1)*QLD];
        a2 += t0[d+2] * wp[(d+2)*QLD];
        a3 += t0[d+3] * wp[(d+3)*QLD];
        a0 += t0[d+4] * wp[(d+4)*QLD];
        a1 += t0[d+5] * wp[(d+5)*QLD];
        a2 += t0[d+6] * wp[(d+6)*QLD];
        a3 += t0[d+7] * wp[(d+7)*QLD];
    }
    g_qp[dc*DIMN + col] = (a0 + a1) + (a2 + a3);
}

// Kernel 1b: reduce the 32 partials (deterministic order) + bias. grid 16, block 128
__global__ void k_q_sum(const float* __restrict__ qkvb) {
    int col = blockIdx.x * 128 + threadIdx.x;
    float a = qkvb[col];
    #pragma unroll
    for (int dc = 0; dc < 32; dc++) a += g_qp[dc*DIMN + col];
    g_q[col] = a;
}

// ---------------------------------------------------------------------------
// Kernel 2: qhat[h, dim] = SCALE * sum_j qkv_w[dim, 2048 + h*128 + j] * q[h*128+j]
// grid (256, 16): 8 dims per CTA (one per warp), block 256, float4 loads.
__global__ void k_qhat(const float* __restrict__ qkvw) {
    int h = blockIdx.y;
    __shared__ float4 qv4[32];
    int tid = threadIdx.x;
    if (tid < 32) qv4[tid] = *reinterpret_cast<const float4*>(&g_q[h*HD + tid*4]);
    __syncthreads();
    int w = tid >> 5, lane = tid & 31;
    int dim = blockIdx.x * 8 + w;
    const float4* wr4 = reinterpret_cast<const float4*>(qkvw + dim*QLD + DIMN + h*HD);
    float4 wv = wr4[lane];
    float4 qv = qv4[lane];
    float p = wv.x*qv.x + wv.y*qv.y + wv.z*qv.z + wv.w*qv.w;
    #pragma unroll
    for (int o = 16; o; o >>= 1) p += __shfl_xor_sync(0xffffffffu, p, o);
    if (lane == 0) g_qhat[h*DIMN + dim] = p * SCALE;
}

// ---------------------------------------------------------------------------
// Kernel 3: scores[b,h,s] = qhat[h,:] . tok[b,s,:]  (tok built on the fly)
// grid (32 stiles, 16 b), block 256 (8 warps). Warp = 4 tokens x 8 heads.
// Lane owns 4 consecutive dims (float4). Double-buffered x prefetch.
__global__ void k_scores(const float* __restrict__ x, const float* __restrict__ pos,
                         const float* __restrict__ cls) {
    int b = blockIdx.y;
    int tid = threadIdx.x, w = tid >> 5, lane = tid & 31;
    int tg = w >> 1;            // token group 0..3
    int hh = (w & 1) * 8;       // head base: 0 or 8
    int s0 = blockIdx.x * 16 + tg * 4;
    __shared__ float qh[NH * 512];   // 32 KB, this d-chunk, all heads

    float acc[8][4];
    #pragma unroll
    for (int h = 0; h < 8; h++)
        #pragma unroll
        for (int j = 0; j < 4; j++) acc[h][j] = 0.f;

    float4 xva[4], xvb[4];
    // prefetch x for slice 0
    {
        int d = lane*4;
        int c = d >> 8, r = d & 255;
        #pragma unroll
        for (int j = 0; j < 4; j++) {
            int s = s0 + j;
            xva[j] = (s == 0) ? *reinterpret_cast<const float4*>(&cls[d])
                              : *reinterpret_cast<const float4*>(&x[b*XB + c*XC + (s-1)*HWSZ + r]);
        }
    }

    for (int ch = 0; ch < 4; ch++) {
        __syncthreads();
        // stage qhat chunk (float4)
        for (int t4 = tid; t4 < NH*128; t4 += 256) {
            int h = t4 >> 7, dd4 = t4 & 127;
            *reinterpret_cast<float4*>(&qh[h*512 + dd4*4]) =
                *reinterpret_cast<const float4*>(&g_qhat[h*DIMN + ch*512 + dd4*4]);
        }
        __syncthreads();
        #pragma unroll
        for (int it = 0; it < 4; it++) {
            int ci = ch*4 + it;                 // global slice 0..15
            float4* cur = (it & 1) ? xvb : xva; // parity static in it
            float4* nxt = (it & 1) ? xva : xvb;
            // prefetch next slice's x (global only; independent of smem)
            if (ci < 15) {
                int dn = (ci+1)*128 + lane*4;
                int cn = dn >> 8, rn = dn & 255;
                #pragma unroll
                for (int j = 0; j < 4; j++) {
                    int s = s0 + j;
                    nxt[j] = (s == 0) ? *reinterpret_cast<const float4*>(&cls[dn])
                                      : *reinterpret_cast<const float4*>(&x[b*XB + cn*XC + (s-1)*HWSZ + rn]);
                }
            }
            // compute current slice
            int dd = it*128 + lane*4;           // within chunk
            int d  = ch*512 + dd;               // absolute dim
            float4 tv[4];
            #pragma unroll
            for (int j = 0; j < 4; j++) {
                float4 pv = *reinterpret_cast<const float4*>(&pos[(s0+j)*DIMN + d]);
                tv[j].x = cur[j].x + pv.x; tv[j].y = cur[j].y + pv.y;
                tv[j].z = cur[j].z + pv.z; tv[j].w = cur[j].w + pv.w;
            }
            #pragma unroll
            for (int h = 0; h < 8; h++) {
                float4 qv = *reinterpret_cast<const float4*>(&qh[(hh + h)*512 + dd]);
                #pragma unroll
                for (int j = 0; j < 4; j++) {
                    acc[h][j] += qv.x*tv[j].x + qv.y*tv[j].y
                               + qv.z*tv[j].z + qv.w*tv[j].w;
                }
            }
        }
    }
    // butterfly reduce (32 outputs per warp)
    #pragma unroll
    for (int o = 16; o; o >>= 1)
        #pragma unroll
        for (int h = 0; h < 8; h++)
            #pragma unroll
            for (int j = 0; j < 4; j++)
                acc[h][j] += __shfl_xor_sync(0xffffffffu, acc[h][j], o);
    // lane (h*4+j) writes its output
    float outv = 0.f;
    #pragma unroll
    for (int h = 0; h < 8; h++)
        #pragma unroll
        for (int j = 0; j < 4; j++)
            if (lane == h*4 + j) outv = acc[h][j];
    int h8 = lane >> 2, j = lane & 3;
    g_sc[(b*NH + hh + h8)*SEQ + s0 + j] = outv;
}

// ---------------------------------------------------------------------------
// Kernel 4: softmax over s (512) per (b,h) row; adds the q.bk bias term.
// grid 256, block 128
__global__ void k_softmax(const float* __restrict__ qkvb) {
    int bh = blockIdx.x;
    int h = bh & 15;
    int tid = threadIdx.x;
    __shared__ float red[128];

    red[tid] = g_q[h*HD + tid] * qkvb[DIMN + h*HD + tid];
    __syncthreads();
    for (int o = 64; o; o >>= 1) { if (tid < o) red[tid] += red[tid + o]; __syncthreads(); }
    float sbias = red[0] * SCALE;
    __syncthreads();

    float* row = g_sc + bh*SEQ;
    float v[4];
    float m = -1e30f;
    #pragma unroll
    for (int j = 0; j < 4; j++) { v[j] = row[tid + j*128] + sbias; m = fmaxf(m, v[j]); }
    red[tid] = m; __syncthreads();
    for (int o = 64; o; o >>= 1) { if (tid < o) red[tid] = fmaxf(red[tid], red[tid + o]); __syncthreads(); }
    m = red[0];
    __syncthreads();
    float s = 0.f;
    #pragma unroll
    for (int j = 0; j < 4; j++) { v[j] = expf(v[j] - m); s += v[j]; }
    red[tid] = s; __syncthreads();
    for (int o = 64; o; o >>= 1) { if (tid < o) red[tid] += red[tid + o]; __syncthreads(); }
    float inv = 1.f / red[0];
    #pragma unroll
    for (int j = 0; j < 4; j++) row[tid + j*128] = v[j] * inv;
}

// ---------------------------------------------------------------------------
// Kernel 5: t partials: g_tp[sq][b,h,dim] over s in [sq*128, sq*128+128).
// grid (4 dchunks, 16 b, 4 sq), block 256. Warp = 128 dims x 8 heads; lane = 4 dims.
// Double-buffered x prefetch.
__global__ void k_t(const float* __restrict__ x, const float* __restrict__ pos,
                    const float* __restrict__ cls) {
    int b = blockIdx.y, sq = blockIdx.z;
    int tid = threadIdx.x, w = tid >> 5, lane = tid & 31;
    int dg = w >> 1;            // dim group 0..3
    int hh = (w & 1) * 8;       // head base
    int dim = blockIdx.x*512 + dg*128 + lane*4;
    int sbase = sq * 128;
    __shared__ float ps[NH][128];  // 8 KB: this quarter's probs
    for (int t = tid; t < NH*128; t += 256) {
        int h = t >> 7, ss = t & 127;
        ps[h][ss] = g_sc[(b*NH + h)*SEQ + sbase + ss];
    }
    __syncthreads();

    int c = dim >> 8, r = dim & 255;          // 4 dims share channel c
    const float* xp = x + b*XB + c*XC + r;    // token s>=1 -> xp + (s-1)*HWSZ
    const float* pp = pos + dim;

    float4 acc[8];
    #pragma unroll
    for (int h = 0; h < 8; h++) acc[h] = make_float4(0.f, 0.f, 0.f, 0.f);

    float4 xa[4], xb[4];
    // preload k=0 tokens (s = sbase..sbase+3; s==0 only when sq==0)
    #pragma unroll
    for (int j = 0; j < 4; j++) {
        int s = sbase + j;
        xa[j] = (s == 0) ? *reinterpret_cast<const float4*>(&cls[dim])
                         : *reinterpret_cast<const float4*>(&xp[(s-1)*HWSZ]);
    }

    #pragma unroll 4
    for (int k2 = 0; k2 < 16; k2++) {
        int k = k2*2;
        // prefetch k+1 (s >= 1 always)
        {
            int s = sbase + (k+1)*4;
            #pragma unroll
            for (int j = 0; j < 4; j++)
                xb[j] = *reinterpret_cast<const float4*>(&xp[(s + j - 1)*HWSZ]);
        }
        // compute k from xa
        {
            int s = sbase + k*4;
            float4 tv[4];
            #pragma unroll
            for (int j = 0; j < 4; j++) {
                float4 pv = *reinterpret_cast<const float4*>(&pp[(s + j)*DIMN]);
                tv[j].x = xa[j].x+pv.x; tv[j].y = xa[j].y+pv.y;
                tv[j].z = xa[j].z+pv.z; tv[j].w = xa[j].w+pv.w;
            }
            #pragma unroll
            for (int h = 0; h < 8; h++) {
                float4 p4 = *reinterpret_cast<const float4*>(&ps[hh + h][k*4]);
                acc[h].x += p4.x*tv[0].x + p4.y*tv[1].x + p4.z*tv[2].x + p4.w*tv[3].x;
                acc[h].y += p4.x*tv[0].y + p4.y*tv[1].y + p4.z*tv[2].y + p4.w*tv[3].y;
                acc[h].z += p4.x*tv[0].z + p4.y*tv[1].z + p4.z*tv[2].z + p4.w*tv[3].z;
                acc[h].w += p4.x*tv[0].w + p4.y*tv[1].w + p4.z*tv[2].w + p4.w*tv[3].w;
            }
        }
        // prefetch k+2 into xa
        if (k2 < 15) {
            int s = sbase + (k+2)*4;
            #pragma unroll
            for (int j = 0; j < 4; j++)
                xa[j] = *reinterpret_cast<const float4*>(&xp[(s + j - 1)*HWSZ]);
        }
        // compute k+1 from xb
        {
            int s = sbase + (k+1)*4;
            float4 tv[4];
            #pragma unroll
            for (int j = 0; j < 4; j++) {
                float4 pv = *reinterpret_cast<const float4*>(&pp[(s + j)*DIMN]);
                tv[j].x = xb[j].x+pv.x; tv[j].y = xb[j].y+pv.y;
                tv[j].z = xb[j].z+pv.z; tv[j].w = xb[j].w+pv.w;
            }
            #pragma unroll
            for (int h = 0; h < 8; h++) {
                float4 p4 = *reinterpret_cast<const float4*>(&ps[hh + h][(k+1)*4]);
                acc[h].x += p4.x*tv[0].x + p4.y*tv[1].x + p4.z*tv[2].x + p4.w*tv[3].x;
                acc[h].y += p4.x*tv[0].y + p4.y*tv[1].y + p4.z*tv[2].y + p4.w*tv[3].y;
                acc[h].z += p4.x*tv[0].z + p4.y*tv[1].z + p4.z*tv[2].z + p4.w*tv[3].z;
                acc[h].w += p4.x*tv[0].w + p4.y*tv[1].w + p4.z*tv[2].w + p4.w*tv[3].w;
            }
        }
    }
    #pragma unroll
    for (int h = 0; h < 8; h++)
        *reinterpret_cast<float4*>(&g_tp[sq][(b*NH + hh + h)*DIMN + dim]) = acc[h];
}

// Kernel 5b: collapse the 4 s-partials (deterministic order).
// grid 512, block 256: 131072 threads x float4 = 524288 floats = BB*NH*DIMN.
__global__ void k_t_sum() {
    int i4 = blockIdx.x * 256 + threadIdx.x;   // float4 index, 131072 total
    float4 a = make_float4(0.f, 0.f, 0.f, 0.f);
    #pragma unroll
    for (int sq = 0; sq < 4; sq++) {
        float4 v = *reinterpret_cast<const float4*>(&g_tp[sq][i4*4]);
        a.x += v.x; a.y += v.y; a.z += v.z; a.w += v.w;
    }
    *reinterpret_cast<float4*>(&g_t[i4*4]) = a;
}

// ---------------------------------------------------------------------------
// Kernel 6a: partial ao over one d-chunk, 64 output cols per CTA.
// grid (2 jb, 16 h, 16 chd), block 256. smem 40 KB.
__global__ void k_avp(const float* __restrict__ qkvw) {
    int jb = blockIdx.x, h = blockIdx.y, chd = blockIdx.z;
    int tid = threadIdx.x;
    int lane = tid & 31, grp = tid >> 5;  // grp: b = grp and grp+8
    __shared__ float ts[16][128];
    __shared__ float ws[128][64];
    // stage t tile
    for (int t = tid; t < 2048; t += 256) {
        int bb = t >> 7, dd = t & 127;
        ts[bb][dd] = g_t[(bb*NH + h)*DIMN + chd*128 + dd];
    }
    // stage Wv tile (128 rows x 64 cols), float4
    const float* wsrc = qkvw + 2*DIMN + h*HD + jb*64;
    for (int t4 = tid; t4 < 2048; t4 += 256) {
        int dd = t4 >> 4, j4 = t4 & 15;
        *reinterpret_cast<float4*>(&ws[dd][j4*4]) =
            *reinterpret_cast<const float4*>(&wsrc[(chd*128 + dd)*QLD + j4*4]);
    }
    __syncthreads();
    float2 a0 = make_float2(0.f, 0.f), a1 = make_float2(0.f, 0.f);
    #pragma unroll 8
    for (int dd = 0; dd < 128; dd++) {
        float2 wv = *reinterpret_cast<const float2*>(&ws[dd][lane*2]);
        float t0 = ts[grp][dd], t1 = ts[grp + 8][dd];
        a0.x += t0*wv.x; a0.y += t0*wv.y;
        a1.x += t1*wv.x; a1.y += t1*wv.y;
    }
    int ocol = h*HD + jb*64 + lane*2;
    *reinterpret_cast<float2*>(&g_aop[chd][ grp     *DIMN + ocol]) = a0;
    *reinterpret_cast<float2*>(&g_aop[chd][(grp + 8)*DIMN + ocol]) = a1;
}

// Kernel 6b: reduce 16 chunk partials + bias -> g_ao. grid 128, block 256.
__global__ void k_ao_sum(const float* __restrict__ qkvb) {
    int idx = blockIdx.x * 256 + threadIdx.x;   // 0 .. 32767
    int col = idx & (DIMN-1);
    float a = qkvb[2*DIMN + col];
    #pragma unroll
    for (int c = 0; c < 16; c++) a += g_aop[c][idx];
    g_ao[idx] = a;
}

// ---------------------------------------------------------------------------
// Kernel 7a: partial proj over one d-chunk, 64 output cols per CTA.
// grid (32 eb, 16 chd), block 256. smem 40 KB.
__global__ void k_projp(const float* __restrict__ pw) {
    int eb = blockIdx.x, chd = blockIdx.y;
    int tid = threadIdx.x;
    int lane = tid & 31, grp = tid >> 5;
    __shared__ float as[16][128];
    __shared__ float ws[128][64];
    for (int t = tid; t < 2048; t += 256) {
        int bb = t >> 7, dd = t & 127;
        as[bb][dd] = g_ao[bb*DIMN + chd*128 + dd];
    }
    const float* wsrc = pw + eb*64;
    for (int t4 = tid; t4 < 2048; t4 += 256) {
        int dd = t4 >> 4, j4 = t4 & 15;
        *reinterpret_cast<float4*>(&ws[dd][j4*4]) =
            *reinterpret_cast<const float4*>(&wsrc[(chd*128 + dd)*DIMN + j4*4]);
    }
    __syncthreads();
    float2 a0 = make_float2(0.f, 0.f), a1 = make_float2(0.f, 0.f);
    #pragma unroll 8
    for (int dd = 0; dd < 128; dd++) {
        float2 wv = *reinterpret_cast<const float2*>(&ws[dd][lane*2]);
        float t0 = as[grp][dd], t1 = as[grp + 8][dd];
        a0.x += t0*wv.x; a0.y += t0*wv.y;
        a1.x += t1*wv.x; a1.y += t1*wv.y;
    }
    int e = eb*64 + lane*2;
    *reinterpret_cast<float2*>(&g_outp[chd][ grp     *DIMN + e]) = a0;
    *reinterpret_cast<float2*>(&g_outp[chd][(grp + 8)*DIMN + e]) = a1;
}

// Kernel 7b: reduce 16 chunk partials + bias -> out. grid 128, block 256.
__global__ void k_out_sum(const float* __restrict__ pb, float* __restrict__ out) {
    int idx = blockIdx.x * 256 + threadIdx.x;
    int e = idx & (DIMN-1);
    float a = pb[e];
    #pragma unroll
    for (int c = 0; c < 16; c++) a += g_outp[c][idx];
    out[idx] = a;
}

// ---------------------------------------------------------------------------
extern "C" void kernel_launch(void* const* d_in, const int* in_sizes, int n_in,
                              void* d_out, int out_size) {
    const float* x    = (const float*)d_in[0];
    const float* pos  = (const float*)d_in[1];
    const float* cls  = (const float*)d_in[2];
    const float* qkvw = (const float*)d_in[3];
    const float* qkvb = (const float*)d_in[4];
    const float* pw   = (const float*)d_in[5];
    const float* pb   = (const float*)d_in[6];
    float* out = (float*)d_out;

    k_q_part <<<dim3(16, 32), 128>>>(pos, cls, qkvw);
    k_q_sum  <<<16, 128>>>(qkvb);
    k_qhat   <<<dim3(256, 16), 256>>>(qkvw);
    k_scores <<<dim3(32, 16), 256>>>(x, pos, cls);
    k_softmax<<<256, 128>>>(qkvb);
    k_t      <<<dim3(4, 16, 4), 256>>>(x, pos, cls);
    k_t_sum  <<<512, 256>>>();
    k_avp    <<<dim3(2, 16, 16), 256>>>(qkvw);
    k_ao_sum <<<128, 256>>>(qkvb);
    k_projp  <<<dim3(32, 16), 256>>>(pw);
    k_out_sum<<<128, 256>>>(pb, out);
}